// round 14
// baseline (speedup 1.0000x reference)
#include <cuda_runtime.h>
#include <cuda_fp16.h>
#include <cstdint>

// Problem constants
#define NUM_B 16384
#define DIM_D 784
#define DIM_L 1024
#define KXP   832          // K of X padded to multiple of 64
#define NRP   896          // recon N padded to multiple of 128
#define LAMBDA 0.3f
#define STEPSZ 0.1f
#define NSTEPS 48
#define MTILES 128
#define NTILES 8
#define TILES_PER_STEP (MTILES * NTILES)   // 1024

// ---------------- scratch (__device__ globals; no allocs allowed) ----------
__device__ float g_B [(size_t)NUM_B * DIM_L];
__device__ float g_U0[(size_t)NUM_B * DIM_L];
__device__ float g_U1[(size_t)NUM_B * DIM_L];
__device__ __half g_Aa[(size_t)NUM_B * DIM_L];
__device__ __half g_Ab[(size_t)NUM_B * DIM_L];
__device__ __half g_Gh[DIM_L * DIM_L];
__device__ __half g_XPh[(size_t)NUM_B * KXP];
__device__ __half g_XPl[(size_t)NUM_B * KXP];
__device__ __half g_WTh[DIM_L * KXP];
__device__ __half g_WTl[DIM_L * KXP];
__device__ __half g_WR [NRP * DIM_L];
__device__ int    g_cnt[NSTEPS * MTILES];   // row completion counters

__device__ __forceinline__ float lca_thresh(float x) {
    return x > LAMBDA ? x - LAMBDA : 0.0f;
}

// ---------------- baseline-ISA tensor helpers ----------
__device__ __forceinline__ uint32_t smem_u32(const void* p) {
    uint32_t a;
    asm("{ .reg .u64 t; cvta.to.shared.u64 t, %1; cvt.u32.u64 %0, t; }"
        : "=r"(a) : "l"(p));
    return a;
}
__device__ __forceinline__ void cp16(uint32_t dst, const void* src) {
    asm volatile("cp.async.cg.shared.global [%0], [%1], 16;"
                 :: "r"(dst), "l"(src) : "memory");
}
__device__ __forceinline__ void cp_commit() {
    asm volatile("cp.async.commit_group;" ::: "memory");
}
template <int N>
__device__ __forceinline__ void cp_wait() {
    asm volatile("cp.async.wait_group %0;" :: "n"(N) : "memory");
}
__device__ __forceinline__ void ldsm_x4(uint32_t* r, uint32_t a) {
    asm volatile("ldmatrix.sync.aligned.m8n8.x4.shared.b16 {%0,%1,%2,%3}, [%4];"
                 : "=r"(r[0]), "=r"(r[1]), "=r"(r[2]), "=r"(r[3]) : "r"(a));
}
__device__ __forceinline__ void mma_f16(float* c, const uint32_t* a, const uint32_t* b) {
    asm volatile(
        "mma.sync.aligned.m16n8k16.row.col.f32.f16.f16.f32 "
        "{%0,%1,%2,%3}, {%4,%5,%6,%7}, {%8,%9}, {%0,%1,%2,%3};"
        : "+f"(c[0]), "+f"(c[1]), "+f"(c[2]), "+f"(c[3])
        : "r"(a[0]), "r"(a[1]), "r"(a[2]), "r"(a[3]), "r"(b[0]), "r"(b[1]));
}

#define BK   64
#define PAD  72
#define TILE_B (128 * PAD * 2)         // 18432 B
#define NCHUNK (DIM_L / BK)            // 16
#define STEP_SMEM (3 * 2 * TILE_B)     // 110592 B -> 2 CTAs/SM

// ============================================================================
// Persistent LCA steps: all 48 steps in ONE launch, R13 pipeline body.
// Dependency: tile (s,m,n) waits until cnt[s-1][m] == 8 (row m complete).
// Consumer polls with a volatile L2 LOAD (no RMW); producers atomicAdd once.
// ============================================================================
__global__ __launch_bounds__(256, 2)
void lca_steps_persistent(const __half* __restrict__ Gh,
                          const float* __restrict__ Bex,
                          __half* __restrict__ Aa, __half* __restrict__ Ab,
                          float* __restrict__ U0, float* __restrict__ U1,
                          int* __restrict__ cnt)
{
    extern __shared__ __align__(16) char dsmem[];
    const uint32_t sb = smem_u32(dsmem);
    constexpr int STAGE_B = 2 * TILE_B;

    const int tid  = threadIdx.x;
    const int lane = tid & 31;
    const int wid  = tid >> 5;
    const int wy   = wid >> 2;
    const int wx   = wid & 3;

    const int a_row = lane & 15;
    const int a_kh  = lane >> 4;
    uint32_t aoffs[4];
    #pragma unroll
    for (int mi = 0; mi < 4; mi++)
        aoffs[mi] = (uint32_t)((wy * 64 + mi * 16 + a_row) * PAD + a_kh * 8) * 2;
    const int b_nr = ((lane >> 4) & 1) * 8 + (lane & 7);
    const int b_kh = (lane >> 3) & 1;
    uint32_t boffs[2];
    #pragma unroll
    for (int p = 0; p < 2; p++)
        boffs[p] = (uint32_t)((wx * 32 + p * 16 + b_nr) * PAD + b_kh * 8) * 2;

    const int c_row = tid >> 3;
    const int c_col = (tid & 7) * 8;
    const int g  = lane >> 2;
    const int tg = lane & 3;

    const int total = NSTEPS * TILES_PER_STEP;

    for (int t = blockIdx.x; t < total; t += gridDim.x) {
        const int s    = t >> 10;
        const int rem  = t & 1023;
        const int mrow = rem >> 3;
        const int m0   = mrow * 128;
        const int n0   = (rem & 7) * 128;

        const __half* ain  = (s & 1) ? Ab : Aa;
        __half*       aout = (s & 1) ? Aa : Ab;
        const float*  uin  = (s & 1) ? U1 : U0;
        float*        uout = (s & 1) ? U0 : U1;

        // ---- dependency wait: read-only L2 polling (no RMW) ----
        if (s > 0 && tid == 0) {
            const volatile int* c = cnt + (s - 1) * MTILES + mrow;
            while (*c < NTILES) __nanosleep(64);
        }
        __syncthreads();

        float acc[4][4][4];
        #pragma unroll
        for (int i = 0; i < 4; i++)
            #pragma unroll
            for (int j = 0; j < 4; j++)
                #pragma unroll
                for (int q = 0; q < 4; q++) acc[i][j][q] = 0.0f;

        auto issue = [&](int c, int stage) {
            const int k0 = c * BK;
            const uint32_t base = sb + stage * STAGE_B;
            #pragma unroll
            for (int u = 0; u < 4; u++) {
                const int row = c_row + u * 32;
                const uint32_t soff = (uint32_t)(row * PAD + c_col) * 2;
                cp16(base + soff, ain + (size_t)(m0 + row) * DIM_L + k0 + c_col);
                cp16(base + TILE_B + soff, Gh + (size_t)(n0 + row) * DIM_L + k0 + c_col);
            }
            cp_commit();
        };

        issue(0, 0);

        int st_c = 0, st_n = 1;
        #pragma unroll 1
        for (int c = 0; c < NCHUNK; c++) {
            if (c + 1 < NCHUNK) {
                issue(c + 1, st_n);
                cp_wait<1>();
            } else {
                cp_wait<0>();
            }
            __syncthreads();

            const uint32_t base = sb + st_c * STAGE_B;
            const uint32_t uB = base + TILE_B;

            #pragma unroll
            for (int kk = 0; kk < BK; kk += 16) {
                const uint32_t kb = (uint32_t)kk * 2;
                uint32_t af[4][4];
                uint32_t bq[2][4];
                #pragma unroll
                for (int p = 0; p < 2; p++)
                    ldsm_x4(bq[p], uB + boffs[p] + kb);
                #pragma unroll
                for (int mi = 0; mi < 4; mi++)
                    ldsm_x4(af[mi], base + aoffs[mi] + kb);
                #pragma unroll
                for (int mi = 0; mi < 4; mi++)
                    #pragma unroll
                    for (int ni = 0; ni < 4; ni++)
                        mma_f16(acc[mi][ni], af[mi], &bq[ni >> 1][(ni & 1) * 2]);
            }
            st_c = st_n;
            st_n = (st_n == 2) ? 0 : st_n + 1;
        }

        // ---- epilogue ----
        #pragma unroll
        for (int mi = 0; mi < 4; mi++) {
            #pragma unroll
            for (int ni = 0; ni < 4; ni++) {
                #pragma unroll
                for (int h = 0; h < 2; h++) {
                    const int r = m0 + wy * 64 + mi * 16 + g + h * 8;
                    const int c0 = n0 + wx * 32 + ni * 8 + tg * 2;
                    const size_t idx = (size_t)r * DIM_L + c0;
                    const float d0 = acc[mi][ni][h * 2 + 0];
                    const float d1 = acc[mi][ni][h * 2 + 1];
                    const float2 u2 = __ldcg((const float2*)(uin + idx));
                    const float2 b2 = *(const float2*)(Bex + idx);
                    const float vx = (1.0f - STEPSZ) * u2.x + STEPSZ * b2.x - STEPSZ * d0;
                    const float vy = (1.0f - STEPSZ) * u2.y + STEPSZ * b2.y - STEPSZ * d1;
                    *(float2*)(uout + idx) = make_float2(vx, vy);
                    const __half h0 = __float2half_rn(lca_thresh(vx));
                    const __half h1 = __float2half_rn(lca_thresh(vy));
                    *(uint32_t*)(aout + idx) =
                        ((uint32_t)__half_as_ushort(h1) << 16) | __half_as_ushort(h0);
                }
            }
        }

        // ---- release ----
        __threadfence();
        __syncthreads();
        if (tid == 0)
            atomicAdd(cnt + s * MTILES + mrow, 1);
    }
}

// ============================================================================
// fp16 mma GEMM (2-stage) for G, b, recon.
//  EPI 2: b      Cout = D fp32, Uout = 0.1D, Aout = fp16(thresh(0.1D))
//  EPI 3: recon  Cout = D fp32, col < DIM_D guard, ld = DIM_D
//  EPI 4: G      Aout(=Gh) = fp16(D - I)
// ============================================================================
template<int NPROD, int EPI>
__global__ __launch_bounds__(256, 2)
void mma_gemm(const __half* __restrict__ A0p, const __half* __restrict__ A1p,
              const __half* __restrict__ Bmp,
              float* __restrict__ Uout,
              __half* __restrict__ Aout,
              float* __restrict__ Cout,
              int Kdim, int ldA, int ldB)
{
    constexpr int STAGE_B = (NPROD + 1) * TILE_B;
    extern __shared__ __align__(16) char dsmem[];
    const uint32_t sb = smem_u32(dsmem);

    const int tid  = threadIdx.x;
    const int lane = tid & 31;
    const int wid  = tid >> 5;
    const int wy   = wid >> 2;
    const int wx   = wid & 3;
    const int m0   = blockIdx.y * 128;
    const int n0   = blockIdx.x * 128;
    const int NC   = Kdim >> 6;

    const int a_row = lane & 15;
    const int a_kh  = lane >> 4;
    uint32_t aoffs[4];
    #pragma unroll
    for (int mi = 0; mi < 4; mi++)
        aoffs[mi] = (uint32_t)((wy * 64 + mi * 16 + a_row) * PAD + a_kh * 8) * 2;

    const int b_nr = ((lane >> 4) & 1) * 8 + (lane & 7);
    const int b_kh = (lane >> 3) & 1;
    uint32_t boffs[2];
    #pragma unroll
    for (int p = 0; p < 2; p++)
        boffs[p] = (uint32_t)((wx * 32 + p * 16 + b_nr) * PAD + b_kh * 8) * 2;

    const int c_row = tid >> 3;
    const int c_col = (tid & 7) * 8;

    float acc[4][4][4];
    #pragma unroll
    for (int i = 0; i < 4; i++)
        #pragma unroll
        for (int j = 0; j < 4; j++)
            #pragma unroll
            for (int q = 0; q < 4; q++) acc[i][j][q] = 0.0f;

    auto issue = [&](int c, int stage) {
        const int k0 = c * BK;
        const uint32_t base = sb + stage * STAGE_B;
        #pragma unroll
        for (int t = 0; t < 4; t++) {
            const int row = c_row + t * 32;
            const uint32_t soff = (uint32_t)(row * PAD + c_col) * 2;
            cp16(base + soff, A0p + (size_t)(m0 + row) * ldA + k0 + c_col);
            if (NPROD == 2)
                cp16(base + TILE_B + soff, A1p + (size_t)(m0 + row) * ldA + k0 + c_col);
            cp16(base + NPROD * TILE_B + soff,
                 Bmp + (size_t)(n0 + row) * ldB + k0 + c_col);
        }
        cp_commit();
    };

    issue(0, 0);

    #pragma unroll 1
    for (int c = 0; c < NC; c++) {
        if (c + 1 < NC) {
            issue(c + 1, (c + 1) & 1);
            cp_wait<1>();
        } else {
            cp_wait<0>();
        }
        __syncthreads();

        const uint32_t base = sb + (c & 1) * STAGE_B;
        const uint32_t uB = base + NPROD * TILE_B;

        #pragma unroll
        for (int kk = 0; kk < BK; kk += 16) {
            const uint32_t kb = (uint32_t)kk * 2;
            uint32_t af[4][4];
            uint32_t bq[2][4];
            #pragma unroll
            for (int p = 0; p < 2; p++)
                ldsm_x4(bq[p], uB + boffs[p] + kb);
            #pragma unroll
            for (int mi = 0; mi < 4; mi++)
                ldsm_x4(af[mi], base + aoffs[mi] + kb);
            #pragma unroll
            for (int mi = 0; mi < 4; mi++)
                #pragma unroll
                for (int ni = 0; ni < 4; ni++)
                    mma_f16(acc[mi][ni], af[mi], &bq[ni >> 1][(ni & 1) * 2]);
            if (NPROD == 2) {
                #pragma unroll
                for (int mi = 0; mi < 4; mi++)
                    ldsm_x4(af[mi], base + TILE_B + aoffs[mi] + kb);
                #pragma unroll
                for (int mi = 0; mi < 4; mi++)
                    #pragma unroll
                    for (int ni = 0; ni < 4; ni++)
                        mma_f16(acc[mi][ni], af[mi], &bq[ni >> 1][(ni & 1) * 2]);
            }
        }
        __syncthreads();
    }

    const int g  = lane >> 2;
    const int tg = lane & 3;
    #pragma unroll
    for (int mi = 0; mi < 4; mi++) {
        #pragma unroll
        for (int ni = 0; ni < 4; ni++) {
            #pragma unroll
            for (int h = 0; h < 2; h++) {
                const int r = m0 + wy * 64 + mi * 16 + g + h * 8;
                const int c0 = n0 + wx * 32 + ni * 8 + tg * 2;
                float d0 = acc[mi][ni][h * 2 + 0];
                float d1 = acc[mi][ni][h * 2 + 1];
                if (EPI == 2) {
                    const size_t idx = (size_t)r * DIM_L + c0;
                    *(float2*)(Cout + idx) = make_float2(d0, d1);
                    const float vx = STEPSZ * d0, vy = STEPSZ * d1;
                    *(float2*)(Uout + idx) = make_float2(vx, vy);
                    const __half h0 = __float2half_rn(lca_thresh(vx));
                    const __half h1 = __float2half_rn(lca_thresh(vy));
                    *(uint32_t*)(Aout + idx) =
                        ((uint32_t)__half_as_ushort(h1) << 16) | __half_as_ushort(h0);
                } else if (EPI == 3) {
                    if (c0 < DIM_D)
                        *(float2*)(Cout + (size_t)r * DIM_D + c0) = make_float2(d0, d1);
                } else { // EPI == 4
                    if (r == c0 + 0) d0 -= 1.0f;
                    if (r == c0 + 1) d1 -= 1.0f;
                    const __half h0 = __float2half_rn(d0);
                    const __half h1 = __float2half_rn(d1);
                    *(uint32_t*)(Aout + (size_t)r * DIM_L + c0) =
                        ((uint32_t)__half_as_ushort(h1) << 16) | __half_as_ushort(h0);
                }
            }
        }
    }
}

// ---------------- conversion kernels (one-time) ----------------
__global__ void split_pad_x(const float* __restrict__ X,
                            __half* __restrict__ hi, __half* __restrict__ lo)
{
    const size_t v = (size_t)blockIdx.x * blockDim.x + threadIdx.x;
    const int row = (int)(v / (KXP / 4));
    const int c4  = (int)(v % (KXP / 4)) * 4;
    uint32_t hp[2] = {0, 0}, lp[2] = {0, 0};
    if (c4 < DIM_D) {
        const float4 x = *(const float4*)(X + (size_t)row * DIM_D + c4);
        const __half h0 = __float2half_rn(x.x), h1 = __float2half_rn(x.y);
        const __half h2 = __float2half_rn(x.z), h3 = __float2half_rn(x.w);
        const __half l0 = __float2half_rn(x.x - __half2float(h0));
        const __half l1 = __float2half_rn(x.y - __half2float(h1));
        const __half l2 = __float2half_rn(x.z - __half2float(h2));
        const __half l3 = __float2half_rn(x.w - __half2float(h3));
        hp[0] = ((uint32_t)__half_as_ushort(h1) << 16) | __half_as_ushort(h0);
        hp[1] = ((uint32_t)__half_as_ushort(h3) << 16) | __half_as_ushort(h2);
        lp[0] = ((uint32_t)__half_as_ushort(l1) << 16) | __half_as_ushort(l0);
        lp[1] = ((uint32_t)__half_as_ushort(l3) << 16) | __half_as_ushort(l2);
    }
    const size_t o = (size_t)row * KXP + c4;
    *(uint2*)(hi + o) = *(const uint2*)hp;
    *(uint2*)(lo + o) = *(const uint2*)lp;
}

__global__ void transpose_w(const float* __restrict__ W,
                            __half* __restrict__ WTh, __half* __restrict__ WTl)
{
    const size_t i = (size_t)blockIdx.x * blockDim.x + threadIdx.x;
    if (i >= (size_t)DIM_L * KXP) return;
    const int n = (int)(i / KXP);
    const int k = (int)(i % KXP);
    const float v = (k < DIM_D) ? W[(size_t)k * DIM_L + n] : 0.0f;
    const __half h = __float2half_rn(v);
    WTh[i] = h;
    WTl[i] = __float2half_rn(v - __half2float(h));
}

__global__ void pad_w(const float* __restrict__ W, __half* __restrict__ WR)
{
    const size_t i = ((size_t)blockIdx.x * blockDim.x + threadIdx.x) * 4;
    if (i >= (size_t)NRP * DIM_L) return;
    const int row = (int)(i / DIM_L);
    uint32_t p[2] = {0, 0};
    if (row < DIM_D) {
        const float4 v = *(const float4*)(W + i);
        p[0] = ((uint32_t)__half_as_ushort(__float2half_rn(v.y)) << 16) |
               __half_as_ushort(__float2half_rn(v.x));
        p[1] = ((uint32_t)__half_as_ushort(__float2half_rn(v.w)) << 16) |
               __half_as_ushort(__float2half_rn(v.z));
    }
    *(uint2*)(WR + i) = *(const uint2*)p;
}

// ============================================================================
extern "C" void kernel_launch(void* const* d_in, const int* in_sizes, int n_in,
                              void* d_out, int out_size) {
    (void)n_in; (void)out_size;

    const float* x = (const float*)d_in[0];
    const float* w = (const float*)d_in[1];
    if (in_sizes[0] == DIM_D * DIM_L) {
        x = (const float*)d_in[1];
        w = (const float*)d_in[0];
    }
    float* out = (float*)d_out;

    float *Bb, *U0, *U1;
    __half *Aa, *Ab, *Gh, *XPh, *XPl, *WTh, *WTl, *WR;
    int* cnt;
    cudaGetSymbolAddress((void**)&Bb,  g_B);
    cudaGetSymbolAddress((void**)&U0,  g_U0);
    cudaGetSymbolAddress((void**)&U1,  g_U1);
    cudaGetSymbolAddress((void**)&Aa,  g_Aa);
    cudaGetSymbolAddress((void**)&Ab,  g_Ab);
    cudaGetSymbolAddress((void**)&Gh,  g_Gh);
    cudaGetSymbolAddress((void**)&XPh, g_XPh);
    cudaGetSymbolAddress((void**)&XPl, g_XPl);
    cudaGetSymbolAddress((void**)&WTh, g_WTh);
    cudaGetSymbolAddress((void**)&WTl, g_WTl);
    cudaGetSymbolAddress((void**)&WR,  g_WR);
    cudaGetSymbolAddress((void**)&cnt, g_cnt);

    const int SM1 = 2 * 2 * TILE_B;   // 73728 (recon)
    const int SM2 = 2 * 3 * TILE_B;   // 110592 (b, G)
    cudaFuncSetAttribute(lca_steps_persistent,
                         cudaFuncAttributeMaxDynamicSharedMemorySize, STEP_SMEM);
    cudaFuncSetAttribute(mma_gemm<1, 3>, cudaFuncAttributeMaxDynamicSharedMemorySize, SM1);
    cudaFuncSetAttribute(mma_gemm<2, 2>, cudaFuncAttributeMaxDynamicSharedMemorySize, SM2);
    cudaFuncSetAttribute(mma_gemm<2, 4>, cudaFuncAttributeMaxDynamicSharedMemorySize, SM2);

    int nsm = 148;
    cudaDeviceGetAttribute(&nsm, cudaDevAttrMultiProcessorCount, 0);
    const int pgrid = 2 * nsm;

    // zero dependency counters (graph-capturable)
    cudaMemsetAsync(cnt, 0, NSTEPS * MTILES * sizeof(int));

    // conversions
    transpose_w<<<(DIM_L * KXP + 255) / 256, 256>>>(w, WTh, WTl);
    split_pad_x<<<(int)(((size_t)NUM_B * KXP / 4) / 256), 256>>>(x, XPh, XPl);
    pad_w<<<(NRP * DIM_L / 4 + 255) / 256, 256>>>(w, WR);

    // Gh = fp16( (WTh+WTl) @ WTh - I )
    mma_gemm<2, 4><<<dim3(8, 8), 256, SM2>>>(
        WTh, WTl, WTh, nullptr, Gh, nullptr, KXP, KXP, KXP);

    // b = X@W (fp16 2-product) + fused u1 = 0.1b, a1 = fp16(thresh(u1))
    mma_gemm<2, 2><<<dim3(8, 128), 256, SM2>>>(
        XPh, XPl, WTh, U0, Aa, Bb, KXP, KXP, KXP);

    // all 48 steps, one persistent launch (s=0 reads Aa/U0; s=47 writes Aa/U0)
    lca_steps_persistent<<<pgrid, 256, STEP_SMEM>>>(Gh, Bb, Aa, Ab, U0, U1, cnt);

    // recon = a_final@W^T (a_final in Aa), N=784 guarded
    mma_gemm<1, 3><<<dim3(7, 128), 256, SM1>>>(
        Aa, nullptr, WR, nullptr, nullptr, out, DIM_L, DIM_L, DIM_L);
}

// round 15
// speedup vs baseline: 1.1067x; 1.1067x over previous
#include <cuda_runtime.h>
#include <cuda_fp16.h>
#include <cstdint>

// Problem constants
#define NUM_B 16384
#define DIM_D 784
#define DIM_L 1024
#define KXP   832          // K of X padded to multiple of 64
#define NRP   896          // recon N padded to multiple of 128
#define LAMBDA 0.3f
#define STEPSZ 0.1f

// ---------------- scratch (__device__ globals; no allocs allowed) ----------
__device__ __half g_Bh[(size_t)NUM_B * DIM_L];        // b in fp16 (storage-rounded)
__device__ float g_U0[(size_t)NUM_B * DIM_L];
__device__ float g_U1[(size_t)NUM_B * DIM_L];
__device__ __half g_Aa[(size_t)NUM_B * DIM_L];        // a ping
__device__ __half g_Ab[(size_t)NUM_B * DIM_L];        // a pong
__device__ __half g_Gh[DIM_L * DIM_L];                // fp16(G)
__device__ __half g_XPh[(size_t)NUM_B * KXP];         // X hi, K-padded
__device__ __half g_XPl[(size_t)NUM_B * KXP];         // X lo
__device__ __half g_WTh[DIM_L * KXP];                 // W^T hi fp16 [L, KXP]
__device__ __half g_WTl[DIM_L * KXP];                 // W^T lo fp16
__device__ __half g_WR [NRP * DIM_L];                 // W fp16 padded [NRP, L]

__device__ __forceinline__ float lca_thresh(float x) {
    return x > LAMBDA ? x - LAMBDA : 0.0f;
}

// ---------------- baseline-ISA tensor helpers ----------
__device__ __forceinline__ uint32_t smem_u32(const void* p) {
    uint32_t a;
    asm("{ .reg .u64 t; cvta.to.shared.u64 t, %1; cvt.u32.u64 %0, t; }"
        : "=r"(a) : "l"(p));
    return a;
}
__device__ __forceinline__ void cp16(uint32_t dst, const void* src) {
    asm volatile("cp.async.cg.shared.global [%0], [%1], 16;"
                 :: "r"(dst), "l"(src) : "memory");
}
__device__ __forceinline__ void cp_commit() {
    asm volatile("cp.async.commit_group;" ::: "memory");
}
template <int N>
__device__ __forceinline__ void cp_wait() {
    asm volatile("cp.async.wait_group %0;" :: "n"(N) : "memory");
}
__device__ __forceinline__ void ldsm_x4(uint32_t* r, uint32_t a) {
    asm volatile("ldmatrix.sync.aligned.m8n8.x4.shared.b16 {%0,%1,%2,%3}, [%4];"
                 : "=r"(r[0]), "=r"(r[1]), "=r"(r[2]), "=r"(r[3]) : "r"(a));
}
__device__ __forceinline__ void mma_f16(float* c, const uint32_t* a, const uint32_t* b) {
    asm volatile(
        "mma.sync.aligned.m16n8k16.row.col.f32.f16.f16.f32 "
        "{%0,%1,%2,%3}, {%4,%5,%6,%7}, {%8,%9}, {%0,%1,%2,%3};"
        : "+f"(c[0]), "+f"(c[1]), "+f"(c[2]), "+f"(c[3])
        : "r"(a[0]), "r"(a[1]), "r"(a[2]), "r"(a[3]), "r"(b[0]), "r"(b[1]));
}

#define BK   64
#define PAD  72                        // fp16/row (144B pitch, conflict-free)
#define TILE_B (128 * PAD * 2)         // 18432 B
#define NCHUNK (DIM_L / BK)            // 16
#define STEP_SMEM (3 * 2 * TILE_B)     // 110592 B -> 2 CTAs/SM

// ============================================================================
// LCA step kernel (R13 body): 3-stage pipeline, one sync per chunk.
// b is read as fp16.  u' = 0.9u + 0.1b - 0.1D; a' = fp16(thresh(u')).
// ============================================================================
__global__ __launch_bounds__(256, 2)
void lca_step(const __half* __restrict__ Ain,
              const __half* __restrict__ Gh,
              const float* __restrict__ Uin,
              const __half* __restrict__ Bex,
              float* __restrict__ Uout,
              __half* __restrict__ Aout)
{
    extern __shared__ __align__(16) char dsmem[];
    const uint32_t sb = smem_u32(dsmem);
    constexpr int STAGE_B = 2 * TILE_B;

    const int tid  = threadIdx.x;
    const int lane = tid & 31;
    const int wid  = tid >> 5;
    const int wy   = wid >> 2;
    const int wx   = wid & 3;
    const int m0   = blockIdx.y * 128;
    const int n0   = blockIdx.x * 128;

    const int a_row = lane & 15;
    const int a_kh  = lane >> 4;
    uint32_t aoffs[4];
    #pragma unroll
    for (int mi = 0; mi < 4; mi++)
        aoffs[mi] = (uint32_t)((wy * 64 + mi * 16 + a_row) * PAD + a_kh * 8) * 2;

    const int b_nr = ((lane >> 4) & 1) * 8 + (lane & 7);
    const int b_kh = (lane >> 3) & 1;
    uint32_t boffs[2];
    #pragma unroll
    for (int p = 0; p < 2; p++)
        boffs[p] = (uint32_t)((wx * 32 + p * 16 + b_nr) * PAD + b_kh * 8) * 2;

    const int c_row = tid >> 3;
    const int c_col = (tid & 7) * 8;

    float acc[4][4][4];
    #pragma unroll
    for (int i = 0; i < 4; i++)
        #pragma unroll
        for (int j = 0; j < 4; j++)
            #pragma unroll
            for (int q = 0; q < 4; q++) acc[i][j][q] = 0.0f;

    auto issue = [&](int c, int stage) {
        const int k0 = c * BK;
        const uint32_t base = sb + stage * STAGE_B;
        #pragma unroll
        for (int u = 0; u < 4; u++) {
            const int row = c_row + u * 32;
            const uint32_t soff = (uint32_t)(row * PAD + c_col) * 2;
            cp16(base + soff, Ain + (size_t)(m0 + row) * DIM_L + k0 + c_col);
            cp16(base + TILE_B + soff, Gh + (size_t)(n0 + row) * DIM_L + k0 + c_col);
        }
        cp_commit();
    };

    issue(0, 0);

    int st_c = 0, st_n = 1;
    #pragma unroll 1
    for (int c = 0; c < NCHUNK; c++) {
        if (c + 1 < NCHUNK) {
            issue(c + 1, st_n);
            cp_wait<1>();
        } else {
            cp_wait<0>();
        }
        __syncthreads();

        const uint32_t base = sb + st_c * STAGE_B;
        const uint32_t uB = base + TILE_B;

        #pragma unroll
        for (int kk = 0; kk < BK; kk += 16) {
            const uint32_t kb = (uint32_t)kk * 2;
            uint32_t af[4][4];
            uint32_t bq[2][4];
            #pragma unroll
            for (int p = 0; p < 2; p++)
                ldsm_x4(bq[p], uB + boffs[p] + kb);
            #pragma unroll
            for (int mi = 0; mi < 4; mi++)
                ldsm_x4(af[mi], base + aoffs[mi] + kb);
            #pragma unroll
            for (int mi = 0; mi < 4; mi++)
                #pragma unroll
                for (int ni = 0; ni < 4; ni++)
                    mma_f16(acc[mi][ni], af[mi], &bq[ni >> 1][(ni & 1) * 2]);
        }
        st_c = st_n;
        st_n = (st_n == 2) ? 0 : st_n + 1;
    }

    // ---------------- epilogue ----------------
    const int g  = lane >> 2;
    const int tg = lane & 3;
    #pragma unroll
    for (int mi = 0; mi < 4; mi++) {
        #pragma unroll
        for (int ni = 0; ni < 4; ni++) {
            #pragma unroll
            for (int h = 0; h < 2; h++) {
                const int r = m0 + wy * 64 + mi * 16 + g + h * 8;
                const int c0 = n0 + wx * 32 + ni * 8 + tg * 2;
                const size_t idx = (size_t)r * DIM_L + c0;
                const float d0 = acc[mi][ni][h * 2 + 0];
                const float d1 = acc[mi][ni][h * 2 + 1];
                const float2 u2 = *(const float2*)(Uin + idx);
                const __half2 bh = *(const __half2*)(Bex + idx);
                const float2 b2 = __half22float2(bh);
                const float vx = (1.0f - STEPSZ) * u2.x + STEPSZ * b2.x - STEPSZ * d0;
                const float vy = (1.0f - STEPSZ) * u2.y + STEPSZ * b2.y - STEPSZ * d1;
                *(float2*)(Uout + idx) = make_float2(vx, vy);
                const __half h0 = __float2half_rn(lca_thresh(vx));
                const __half h1 = __float2half_rn(lca_thresh(vy));
                *(uint32_t*)(Aout + idx) =
                    ((uint32_t)__half_as_ushort(h1) << 16) | __half_as_ushort(h0);
            }
        }
    }
}

// ============================================================================
// fp16 mma GEMM (2-stage) for G, b, recon.
//  EPI 2: b      Bout = fp16(D), Uout = 0.1D (fp32), Aout = fp16(thresh(0.1D))
//  EPI 3: recon  Cout = D fp32, col < DIM_D guard, ld = DIM_D
//  EPI 4: G      Aout(=Gh) = fp16(D - I)
// ============================================================================
template<int NPROD, int EPI>
__global__ __launch_bounds__(256, 2)
void mma_gemm(const __half* __restrict__ A0p, const __half* __restrict__ A1p,
              const __half* __restrict__ Bmp,
              float* __restrict__ Uout,
              __half* __restrict__ Aout,
              __half* __restrict__ Bout,
              float* __restrict__ Cout,
              int Kdim, int ldA, int ldB)
{
    constexpr int STAGE_B = (NPROD + 1) * TILE_B;
    extern __shared__ __align__(16) char dsmem[];
    const uint32_t sb = smem_u32(dsmem);

    const int tid  = threadIdx.x;
    const int lane = tid & 31;
    const int wid  = tid >> 5;
    const int wy   = wid >> 2;
    const int wx   = wid & 3;
    const int m0   = blockIdx.y * 128;
    const int n0   = blockIdx.x * 128;
    const int NC   = Kdim >> 6;

    const int a_row = lane & 15;
    const int a_kh  = lane >> 4;
    uint32_t aoffs[4];
    #pragma unroll
    for (int mi = 0; mi < 4; mi++)
        aoffs[mi] = (uint32_t)((wy * 64 + mi * 16 + a_row) * PAD + a_kh * 8) * 2;

    const int b_nr = ((lane >> 4) & 1) * 8 + (lane & 7);
    const int b_kh = (lane >> 3) & 1;
    uint32_t boffs[2];
    #pragma unroll
    for (int p = 0; p < 2; p++)
        boffs[p] = (uint32_t)((wx * 32 + p * 16 + b_nr) * PAD + b_kh * 8) * 2;

    const int c_row = tid >> 3;
    const int c_col = (tid & 7) * 8;

    float acc[4][4][4];
    #pragma unroll
    for (int i = 0; i < 4; i++)
        #pragma unroll
        for (int j = 0; j < 4; j++)
            #pragma unroll
            for (int q = 0; q < 4; q++) acc[i][j][q] = 0.0f;

    auto issue = [&](int c, int stage) {
        const int k0 = c * BK;
        const uint32_t base = sb + stage * STAGE_B;
        #pragma unroll
        for (int t = 0; t < 4; t++) {
            const int row = c_row + t * 32;
            const uint32_t soff = (uint32_t)(row * PAD + c_col) * 2;
            cp16(base + soff, A0p + (size_t)(m0 + row) * ldA + k0 + c_col);
            if (NPROD == 2)
                cp16(base + TILE_B + soff, A1p + (size_t)(m0 + row) * ldA + k0 + c_col);
            cp16(base + NPROD * TILE_B + soff,
                 Bmp + (size_t)(n0 + row) * ldB + k0 + c_col);
        }
        cp_commit();
    };

    issue(0, 0);

    #pragma unroll 1
    for (int c = 0; c < NC; c++) {
        if (c + 1 < NC) {
            issue(c + 1, (c + 1) & 1);
            cp_wait<1>();
        } else {
            cp_wait<0>();
        }
        __syncthreads();

        const uint32_t base = sb + (c & 1) * STAGE_B;
        const uint32_t uB = base + NPROD * TILE_B;

        #pragma unroll
        for (int kk = 0; kk < BK; kk += 16) {
            const uint32_t kb = (uint32_t)kk * 2;
            uint32_t af[4][4];
            uint32_t bq[2][4];
            #pragma unroll
            for (int p = 0; p < 2; p++)
                ldsm_x4(bq[p], uB + boffs[p] + kb);
            #pragma unroll
            for (int mi = 0; mi < 4; mi++)
                ldsm_x4(af[mi], base + aoffs[mi] + kb);
            #pragma unroll
            for (int mi = 0; mi < 4; mi++)
                #pragma unroll
                for (int ni = 0; ni < 4; ni++)
                    mma_f16(acc[mi][ni], af[mi], &bq[ni >> 1][(ni & 1) * 2]);
            if (NPROD == 2) {
                #pragma unroll
                for (int mi = 0; mi < 4; mi++)
                    ldsm_x4(af[mi], base + TILE_B + aoffs[mi] + kb);
                #pragma unroll
                for (int mi = 0; mi < 4; mi++)
                    #pragma unroll
                    for (int ni = 0; ni < 4; ni++)
                        mma_f16(acc[mi][ni], af[mi], &bq[ni >> 1][(ni & 1) * 2]);
            }
        }
        __syncthreads();
    }

    const int g  = lane >> 2;
    const int tg = lane & 3;
    #pragma unroll
    for (int mi = 0; mi < 4; mi++) {
        #pragma unroll
        for (int ni = 0; ni < 4; ni++) {
            #pragma unroll
            for (int h = 0; h < 2; h++) {
                const int r = m0 + wy * 64 + mi * 16 + g + h * 8;
                const int c0 = n0 + wx * 32 + ni * 8 + tg * 2;
                float d0 = acc[mi][ni][h * 2 + 0];
                float d1 = acc[mi][ni][h * 2 + 1];
                if (EPI == 2) {
                    const size_t idx = (size_t)r * DIM_L + c0;
                    // b stored fp16 (storage rounding only); u1 uses full fp32 d
                    const __half bh0 = __float2half_rn(d0);
                    const __half bh1 = __float2half_rn(d1);
                    *(uint32_t*)(Bout + idx) =
                        ((uint32_t)__half_as_ushort(bh1) << 16) | __half_as_ushort(bh0);
                    const float vx = STEPSZ * d0, vy = STEPSZ * d1;
                    *(float2*)(Uout + idx) = make_float2(vx, vy);
                    const __half h0 = __float2half_rn(lca_thresh(vx));
                    const __half h1 = __float2half_rn(lca_thresh(vy));
                    *(uint32_t*)(Aout + idx) =
                        ((uint32_t)__half_as_ushort(h1) << 16) | __half_as_ushort(h0);
                } else if (EPI == 3) {
                    if (c0 < DIM_D)
                        *(float2*)(Cout + (size_t)r * DIM_D + c0) = make_float2(d0, d1);
                } else { // EPI == 4
                    if (r == c0 + 0) d0 -= 1.0f;
                    if (r == c0 + 1) d1 -= 1.0f;
                    const __half h0 = __float2half_rn(d0);
                    const __half h1 = __float2half_rn(d1);
                    *(uint32_t*)(Aout + (size_t)r * DIM_L + c0) =
                        ((uint32_t)__half_as_ushort(h1) << 16) | __half_as_ushort(h0);
                }
            }
        }
    }
}

// ---------------- conversion kernels (one-time) ----------------
__global__ void split_pad_x(const float* __restrict__ X,
                            __half* __restrict__ hi, __half* __restrict__ lo)
{
    const size_t v = (size_t)blockIdx.x * blockDim.x + threadIdx.x;
    const int row = (int)(v / (KXP / 4));
    const int c4  = (int)(v % (KXP / 4)) * 4;
    uint32_t hp[2] = {0, 0}, lp[2] = {0, 0};
    if (c4 < DIM_D) {
        const float4 x = *(const float4*)(X + (size_t)row * DIM_D + c4);
        const __half h0 = __float2half_rn(x.x), h1 = __float2half_rn(x.y);
        const __half h2 = __float2half_rn(x.z), h3 = __float2half_rn(x.w);
        const __half l0 = __float2half_rn(x.x - __half2float(h0));
        const __half l1 = __float2half_rn(x.y - __half2float(h1));
        const __half l2 = __float2half_rn(x.z - __half2float(h2));
        const __half l3 = __float2half_rn(x.w - __half2float(h3));
        hp[0] = ((uint32_t)__half_as_ushort(h1) << 16) | __half_as_ushort(h0);
        hp[1] = ((uint32_t)__half_as_ushort(h3) << 16) | __half_as_ushort(h2);
        lp[0] = ((uint32_t)__half_as_ushort(l1) << 16) | __half_as_ushort(l0);
        lp[1] = ((uint32_t)__half_as_ushort(l3) << 16) | __half_as_ushort(l2);
    }
    const size_t o = (size_t)row * KXP + c4;
    *(uint2*)(hi + o) = *(const uint2*)hp;
    *(uint2*)(lo + o) = *(const uint2*)lp;
}

__global__ void transpose_w(const float* __restrict__ W,
                            __half* __restrict__ WTh, __half* __restrict__ WTl)
{
    const size_t i = (size_t)blockIdx.x * blockDim.x + threadIdx.x;
    if (i >= (size_t)DIM_L * KXP) return;
    const int n = (int)(i / KXP);
    const int k = (int)(i % KXP);
    const float v = (k < DIM_D) ? W[(size_t)k * DIM_L + n] : 0.0f;
    const __half h = __float2half_rn(v);
    WTh[i] = h;
    WTl[i] = __float2half_rn(v - __half2float(h));
}

__global__ void pad_w(const float* __restrict__ W, __half* __restrict__ WR)
{
    const size_t i = ((size_t)blockIdx.x * blockDim.x + threadIdx.x) * 4;
    if (i >= (size_t)NRP * DIM_L) return;
    const int row = (int)(i / DIM_L);
    uint32_t p[2] = {0, 0};
    if (row < DIM_D) {
        const float4 v = *(const float4*)(W + i);
        p[0] = ((uint32_t)__half_as_ushort(__float2half_rn(v.y)) << 16) |
               __half_as_ushort(__float2half_rn(v.x));
        p[1] = ((uint32_t)__half_as_ushort(__float2half_rn(v.w)) << 16) |
               __half_as_ushort(__float2half_rn(v.z));
    }
    *(uint2*)(WR + i) = *(const uint2*)p;
}

// ============================================================================
extern "C" void kernel_launch(void* const* d_in, const int* in_sizes, int n_in,
                              void* d_out, int out_size) {
    (void)n_in; (void)out_size;

    const float* x = (const float*)d_in[0];
    const float* w = (const float*)d_in[1];
    if (in_sizes[0] == DIM_D * DIM_L) {
        x = (const float*)d_in[1];
        w = (const float*)d_in[0];
    }
    float* out = (float*)d_out;

    float *U0, *U1;
    __half *Bh, *Aa, *Ab, *Gh, *XPh, *XPl, *WTh, *WTl, *WR;
    cudaGetSymbolAddress((void**)&Bh,  g_Bh);
    cudaGetSymbolAddress((void**)&U0,  g_U0);
    cudaGetSymbolAddress((void**)&U1,  g_U1);
    cudaGetSymbolAddress((void**)&Aa,  g_Aa);
    cudaGetSymbolAddress((void**)&Ab,  g_Ab);
    cudaGetSymbolAddress((void**)&Gh,  g_Gh);
    cudaGetSymbolAddress((void**)&XPh, g_XPh);
    cudaGetSymbolAddress((void**)&XPl, g_XPl);
    cudaGetSymbolAddress((void**)&WTh, g_WTh);
    cudaGetSymbolAddress((void**)&WTl, g_WTl);
    cudaGetSymbolAddress((void**)&WR,  g_WR);

    const int SM1 = 2 * 2 * TILE_B;   // 73728 (recon)
    const int SM2 = 2 * 3 * TILE_B;   // 110592 (b, G)
    cudaFuncSetAttribute(lca_step, cudaFuncAttributeMaxDynamicSharedMemorySize, STEP_SMEM);
    cudaFuncSetAttribute(mma_gemm<1, 3>, cudaFuncAttributeMaxDynamicSharedMemorySize, SM1);
    cudaFuncSetAttribute(mma_gemm<2, 2>, cudaFuncAttributeMaxDynamicSharedMemorySize, SM2);
    cudaFuncSetAttribute(mma_gemm<2, 4>, cudaFuncAttributeMaxDynamicSharedMemorySize, SM2);

    // conversions
    transpose_w<<<(DIM_L * KXP + 255) / 256, 256>>>(w, WTh, WTl);
    split_pad_x<<<(int)(((size_t)NUM_B * KXP / 4) / 256), 256>>>(x, XPh, XPl);
    pad_w<<<(NRP * DIM_L / 4 + 255) / 256, 256>>>(w, WR);

    // Gh = fp16( (WTh+WTl) @ WTh - I )
    mma_gemm<2, 4><<<dim3(8, 8), 256, SM2>>>(
        WTh, WTl, WTh, nullptr, Gh, nullptr, nullptr, KXP, KXP, KXP);

    // b = X@W (fp16 2-product, fp32 accum) -> bh fp16, u1 = 0.1b, a1 = thresh
    mma_gemm<2, 2><<<dim3(8, 128), 256, SM2>>>(
        XPh, XPl, WTh, U0, Aa, Bh, nullptr, KXP, KXP, KXP);

    // steps 2..49 (single-product fp16, 3-stage single-sync pipeline, b fp16)
    float* uin = U0;  float* uout = U1;
    __half *ain = Aa, *aout = Ab;
    for (int s = 0; s < 48; s++) {
        lca_step<<<dim3(8, 128), 256, STEP_SMEM>>>(
            ain, Gh, uin, Bh, uout, aout);
        float* tu = uin; uin = uout; uout = tu;
        __half* ta = ain; ain = aout; aout = ta;
    }
    // After the final swap, the last-written activations are in `ain`.

    // recon = a_final@W^T (single-product fp16), N=784 guarded
    mma_gemm<1, 3><<<dim3(7, 128), 256, SM1>>>(
        ain, nullptr, WR, nullptr, nullptr, nullptr, out, DIM_L, DIM_L, DIM_L);
}

// round 16
// speedup vs baseline: 1.1564x; 1.0449x over previous
#include <cuda_runtime.h>
#include <cuda_fp16.h>
#include <cstdint>

// Problem constants
#define NUM_B 16384
#define DIM_D 784
#define DIM_L 1024
#define KXP   832          // K of X padded to multiple of 64
#define NRP   896          // recon N padded to multiple of 128
#define LAMBDA 0.3f
#define STEPSZ 0.1f

// ---------------- scratch (__device__ globals; no allocs allowed) ----------
__device__ __half g_Bh[(size_t)NUM_B * DIM_L];        // b fp16 (storage-rounded)
__device__ __half g_U0[(size_t)NUM_B * DIM_L];        // u fp16 ping
__device__ __half g_U1[(size_t)NUM_B * DIM_L];        // u fp16 pong
__device__ __half g_Aa[(size_t)NUM_B * DIM_L];        // a ping
__device__ __half g_Ab[(size_t)NUM_B * DIM_L];        // a pong
__device__ __half g_Gh[DIM_L * DIM_L];                // fp16(G)
__device__ __half g_XPh[(size_t)NUM_B * KXP];         // X hi, K-padded
__device__ __half g_XPl[(size_t)NUM_B * KXP];         // X lo
__device__ __half g_WTh[DIM_L * KXP];                 // W^T hi fp16 [L, KXP]
__device__ __half g_WTl[DIM_L * KXP];                 // W^T lo fp16
__device__ __half g_WR [NRP * DIM_L];                 // W fp16 padded [NRP, L]

__device__ __forceinline__ float lca_thresh(float x) {
    return x > LAMBDA ? x - LAMBDA : 0.0f;
}

// ---------------- baseline-ISA tensor helpers ----------
__device__ __forceinline__ uint32_t smem_u32(const void* p) {
    uint32_t a;
    asm("{ .reg .u64 t; cvta.to.shared.u64 t, %1; cvt.u32.u64 %0, t; }"
        : "=r"(a) : "l"(p));
    return a;
}
__device__ __forceinline__ void cp16(uint32_t dst, const void* src) {
    asm volatile("cp.async.cg.shared.global [%0], [%1], 16;"
                 :: "r"(dst), "l"(src) : "memory");
}
__device__ __forceinline__ void cp_commit() {
    asm volatile("cp.async.commit_group;" ::: "memory");
}
template <int N>
__device__ __forceinline__ void cp_wait() {
    asm volatile("cp.async.wait_group %0;" :: "n"(N) : "memory");
}
__device__ __forceinline__ void ldsm_x4(uint32_t* r, uint32_t a) {
    asm volatile("ldmatrix.sync.aligned.m8n8.x4.shared.b16 {%0,%1,%2,%3}, [%4];"
                 : "=r"(r[0]), "=r"(r[1]), "=r"(r[2]), "=r"(r[3]) : "r"(a));
}
__device__ __forceinline__ void mma_f16(float* c, const uint32_t* a, const uint32_t* b) {
    asm volatile(
        "mma.sync.aligned.m16n8k16.row.col.f32.f16.f16.f32 "
        "{%0,%1,%2,%3}, {%4,%5,%6,%7}, {%8,%9}, {%0,%1,%2,%3};"
        : "+f"(c[0]), "+f"(c[1]), "+f"(c[2]), "+f"(c[3])
        : "r"(a[0]), "r"(a[1]), "r"(a[2]), "r"(a[3]), "r"(b[0]), "r"(b[1]));
}

#define BK   64
#define PAD  72                        // fp16/row (144B pitch, conflict-free)
#define TILE_B (128 * PAD * 2)         // 18432 B
#define NCHUNK (DIM_L / BK)            // 16
#define STEP_SMEM (3 * 2 * TILE_B)     // 110592 B -> 2 CTAs/SM

// ============================================================================
// LCA step kernel (R13 body): 3-stage pipeline, one sync per chunk.
// u and b both fp16 in memory; update computed in fp32, storage rounded.
// ============================================================================
__global__ __launch_bounds__(256, 2)
void lca_step(const __half* __restrict__ Ain,
              const __half* __restrict__ Gh,
              const __half* __restrict__ Uin,
              const __half* __restrict__ Bex,
              __half* __restrict__ Uout,
              __half* __restrict__ Aout)
{
    extern __shared__ __align__(16) char dsmem[];
    const uint32_t sb = smem_u32(dsmem);
    constexpr int STAGE_B = 2 * TILE_B;

    const int tid  = threadIdx.x;
    const int lane = tid & 31;
    const int wid  = tid >> 5;
    const int wy   = wid >> 2;
    const int wx   = wid & 3;
    const int m0   = blockIdx.y * 128;
    const int n0   = blockIdx.x * 128;

    const int a_row = lane & 15;
    const int a_kh  = lane >> 4;
    uint32_t aoffs[4];
    #pragma unroll
    for (int mi = 0; mi < 4; mi++)
        aoffs[mi] = (uint32_t)((wy * 64 + mi * 16 + a_row) * PAD + a_kh * 8) * 2;

    const int b_nr = ((lane >> 4) & 1) * 8 + (lane & 7);
    const int b_kh = (lane >> 3) & 1;
    uint32_t boffs[2];
    #pragma unroll
    for (int p = 0; p < 2; p++)
        boffs[p] = (uint32_t)((wx * 32 + p * 16 + b_nr) * PAD + b_kh * 8) * 2;

    const int c_row = tid >> 3;
    const int c_col = (tid & 7) * 8;

    float acc[4][4][4];
    #pragma unroll
    for (int i = 0; i < 4; i++)
        #pragma unroll
        for (int j = 0; j < 4; j++)
            #pragma unroll
            for (int q = 0; q < 4; q++) acc[i][j][q] = 0.0f;

    auto issue = [&](int c, int stage) {
        const int k0 = c * BK;
        const uint32_t base = sb + stage * STAGE_B;
        #pragma unroll
        for (int u = 0; u < 4; u++) {
            const int row = c_row + u * 32;
            const uint32_t soff = (uint32_t)(row * PAD + c_col) * 2;
            cp16(base + soff, Ain + (size_t)(m0 + row) * DIM_L + k0 + c_col);
            cp16(base + TILE_B + soff, Gh + (size_t)(n0 + row) * DIM_L + k0 + c_col);
        }
        cp_commit();
    };

    issue(0, 0);

    int st_c = 0, st_n = 1;
    #pragma unroll 1
    for (int c = 0; c < NCHUNK; c++) {
        if (c + 1 < NCHUNK) {
            issue(c + 1, st_n);
            cp_wait<1>();
        } else {
            cp_wait<0>();
        }
        __syncthreads();

        const uint32_t base = sb + st_c * STAGE_B;
        const uint32_t uB = base + TILE_B;

        #pragma unroll
        for (int kk = 0; kk < BK; kk += 16) {
            const uint32_t kb = (uint32_t)kk * 2;
            uint32_t af[4][4];
            uint32_t bq[2][4];
            #pragma unroll
            for (int p = 0; p < 2; p++)
                ldsm_x4(bq[p], uB + boffs[p] + kb);
            #pragma unroll
            for (int mi = 0; mi < 4; mi++)
                ldsm_x4(af[mi], base + aoffs[mi] + kb);
            #pragma unroll
            for (int mi = 0; mi < 4; mi++)
                #pragma unroll
                for (int ni = 0; ni < 4; ni++)
                    mma_f16(acc[mi][ni], af[mi], &bq[ni >> 1][(ni & 1) * 2]);
        }
        st_c = st_n;
        st_n = (st_n == 2) ? 0 : st_n + 1;
    }

    // ---------------- epilogue (u fp16 in/out; math in fp32) ----------------
    const int g  = lane >> 2;
    const int tg = lane & 3;
    #pragma unroll
    for (int mi = 0; mi < 4; mi++) {
        #pragma unroll
        for (int ni = 0; ni < 4; ni++) {
            #pragma unroll
            for (int h = 0; h < 2; h++) {
                const int r = m0 + wy * 64 + mi * 16 + g + h * 8;
                const int c0 = n0 + wx * 32 + ni * 8 + tg * 2;
                const size_t idx = (size_t)r * DIM_L + c0;
                const float d0 = acc[mi][ni][h * 2 + 0];
                const float d1 = acc[mi][ni][h * 2 + 1];
                const float2 u2 = __half22float2(*(const __half2*)(Uin + idx));
                const float2 b2 = __half22float2(*(const __half2*)(Bex + idx));
                const float vx = (1.0f - STEPSZ) * u2.x + STEPSZ * b2.x - STEPSZ * d0;
                const float vy = (1.0f - STEPSZ) * u2.y + STEPSZ * b2.y - STEPSZ * d1;
                const __half uh0 = __float2half_rn(vx);
                const __half uh1 = __float2half_rn(vy);
                *(uint32_t*)(Uout + idx) =
                    ((uint32_t)__half_as_ushort(uh1) << 16) | __half_as_ushort(uh0);
                // a from the UNROUNDED update (closer to true dynamics)
                const __half h0 = __float2half_rn(lca_thresh(vx));
                const __half h1 = __float2half_rn(lca_thresh(vy));
                *(uint32_t*)(Aout + idx) =
                    ((uint32_t)__half_as_ushort(h1) << 16) | __half_as_ushort(h0);
            }
        }
    }
}

// ============================================================================
// fp16 mma GEMM (2-stage) for G, b, recon.
//  EPI 2: b      Bout = fp16(D), Uout = fp16(0.1D), Aout = fp16(thresh(0.1D))
//  EPI 3: recon  Cout = D fp32, col < DIM_D guard, ld = DIM_D
//  EPI 4: G      Aout(=Gh) = fp16(D - I)
// ============================================================================
template<int NPROD, int EPI>
__global__ __launch_bounds__(256, 2)
void mma_gemm(const __half* __restrict__ A0p, const __half* __restrict__ A1p,
              const __half* __restrict__ Bmp,
              __half* __restrict__ Uout,
              __half* __restrict__ Aout,
              __half* __restrict__ Bout,
              float* __restrict__ Cout,
              int Kdim, int ldA, int ldB)
{
    constexpr int STAGE_B = (NPROD + 1) * TILE_B;
    extern __shared__ __align__(16) char dsmem[];
    const uint32_t sb = smem_u32(dsmem);

    const int tid  = threadIdx.x;
    const int lane = tid & 31;
    const int wid  = tid >> 5;
    const int wy   = wid >> 2;
    const int wx   = wid & 3;
    const int m0   = blockIdx.y * 128;
    const int n0   = blockIdx.x * 128;
    const int NC   = Kdim >> 6;

    const int a_row = lane & 15;
    const int a_kh  = lane >> 4;
    uint32_t aoffs[4];
    #pragma unroll
    for (int mi = 0; mi < 4; mi++)
        aoffs[mi] = (uint32_t)((wy * 64 + mi * 16 + a_row) * PAD + a_kh * 8) * 2;

    const int b_nr = ((lane >> 4) & 1) * 8 + (lane & 7);
    const int b_kh = (lane >> 3) & 1;
    uint32_t boffs[2];
    #pragma unroll
    for (int p = 0; p < 2; p++)
        boffs[p] = (uint32_t)((wx * 32 + p * 16 + b_nr) * PAD + b_kh * 8) * 2;

    const int c_row = tid >> 3;
    const int c_col = (tid & 7) * 8;

    float acc[4][4][4];
    #pragma unroll
    for (int i = 0; i < 4; i++)
        #pragma unroll
        for (int j = 0; j < 4; j++)
            #pragma unroll
            for (int q = 0; q < 4; q++) acc[i][j][q] = 0.0f;

    auto issue = [&](int c, int stage) {
        const int k0 = c * BK;
        const uint32_t base = sb + stage * STAGE_B;
        #pragma unroll
        for (int t = 0; t < 4; t++) {
            const int row = c_row + t * 32;
            const uint32_t soff = (uint32_t)(row * PAD + c_col) * 2;
            cp16(base + soff, A0p + (size_t)(m0 + row) * ldA + k0 + c_col);
            if (NPROD == 2)
                cp16(base + TILE_B + soff, A1p + (size_t)(m0 + row) * ldA + k0 + c_col);
            cp16(base + NPROD * TILE_B + soff,
                 Bmp + (size_t)(n0 + row) * ldB + k0 + c_col);
        }
        cp_commit();
    };

    issue(0, 0);

    #pragma unroll 1
    for (int c = 0; c < NC; c++) {
        if (c + 1 < NC) {
            issue(c + 1, (c + 1) & 1);
            cp_wait<1>();
        } else {
            cp_wait<0>();
        }
        __syncthreads();

        const uint32_t base = sb + (c & 1) * STAGE_B;
        const uint32_t uB = base + NPROD * TILE_B;

        #pragma unroll
        for (int kk = 0; kk < BK; kk += 16) {
            const uint32_t kb = (uint32_t)kk * 2;
            uint32_t af[4][4];
            uint32_t bq[2][4];
            #pragma unroll
            for (int p = 0; p < 2; p++)
                ldsm_x4(bq[p], uB + boffs[p] + kb);
            #pragma unroll
            for (int mi = 0; mi < 4; mi++)
                ldsm_x4(af[mi], base + aoffs[mi] + kb);
            #pragma unroll
            for (int mi = 0; mi < 4; mi++)
                #pragma unroll
                for (int ni = 0; ni < 4; ni++)
                    mma_f16(acc[mi][ni], af[mi], &bq[ni >> 1][(ni & 1) * 2]);
            if (NPROD == 2) {
                #pragma unroll
                for (int mi = 0; mi < 4; mi++)
                    ldsm_x4(af[mi], base + TILE_B + aoffs[mi] + kb);
                #pragma unroll
                for (int mi = 0; mi < 4; mi++)
                    #pragma unroll
                    for (int ni = 0; ni < 4; ni++)
                        mma_f16(acc[mi][ni], af[mi], &bq[ni >> 1][(ni & 1) * 2]);
            }
        }
        __syncthreads();
    }

    const int g  = lane >> 2;
    const int tg = lane & 3;
    #pragma unroll
    for (int mi = 0; mi < 4; mi++) {
        #pragma unroll
        for (int ni = 0; ni < 4; ni++) {
            #pragma unroll
            for (int h = 0; h < 2; h++) {
                const int r = m0 + wy * 64 + mi * 16 + g + h * 8;
                const int c0 = n0 + wx * 32 + ni * 8 + tg * 2;
                float d0 = acc[mi][ni][h * 2 + 0];
                float d1 = acc[mi][ni][h * 2 + 1];
                if (EPI == 2) {
                    const size_t idx = (size_t)r * DIM_L + c0;
                    const __half bh0 = __float2half_rn(d0);
                    const __half bh1 = __float2half_rn(d1);
                    *(uint32_t*)(Bout + idx) =
                        ((uint32_t)__half_as_ushort(bh1) << 16) | __half_as_ushort(bh0);
                    const float vx = STEPSZ * d0, vy = STEPSZ * d1;
                    const __half uh0 = __float2half_rn(vx);
                    const __half uh1 = __float2half_rn(vy);
                    *(uint32_t*)(Uout + idx) =
                        ((uint32_t)__half_as_ushort(uh1) << 16) | __half_as_ushort(uh0);
                    const __half h0 = __float2half_rn(lca_thresh(vx));
                    const __half h1 = __float2half_rn(lca_thresh(vy));
                    *(uint32_t*)(Aout + idx) =
                        ((uint32_t)__half_as_ushort(h1) << 16) | __half_as_ushort(h0);
                } else if (EPI == 3) {
                    if (c0 < DIM_D)
                        *(float2*)(Cout + (size_t)r * DIM_D + c0) = make_float2(d0, d1);
                } else { // EPI == 4
                    if (r == c0 + 0) d0 -= 1.0f;
                    if (r == c0 + 1) d1 -= 1.0f;
                    const __half h0 = __float2half_rn(d0);
                    const __half h1 = __float2half_rn(d1);
                    *(uint32_t*)(Aout + (size_t)r * DIM_L + c0) =
                        ((uint32_t)__half_as_ushort(h1) << 16) | __half_as_ushort(h0);
                }
            }
        }
    }
}

// ---------------- conversion kernels (one-time) ----------------
__global__ void split_pad_x(const float* __restrict__ X,
                            __half* __restrict__ hi, __half* __restrict__ lo)
{
    const size_t v = (size_t)blockIdx.x * blockDim.x + threadIdx.x;
    const int row = (int)(v / (KXP / 4));
    const int c4  = (int)(v % (KXP / 4)) * 4;
    uint32_t hp[2] = {0, 0}, lp[2] = {0, 0};
    if (c4 < DIM_D) {
        const float4 x = *(const float4*)(X + (size_t)row * DIM_D + c4);
        const __half h0 = __float2half_rn(x.x), h1 = __float2half_rn(x.y);
        const __half h2 = __float2half_rn(x.z), h3 = __float2half_rn(x.w);
        const __half l0 = __float2half_rn(x.x - __half2float(h0));
        const __half l1 = __float2half_rn(x.y - __half2float(h1));
        const __half l2 = __float2half_rn(x.z - __half2float(h2));
        const __half l3 = __float2half_rn(x.w - __half2float(h3));
        hp[0] = ((uint32_t)__half_as_ushort(h1) << 16) | __half_as_ushort(h0);
        hp[1] = ((uint32_t)__half_as_ushort(h3) << 16) | __half_as_ushort(h2);
        lp[0] = ((uint32_t)__half_as_ushort(l1) << 16) | __half_as_ushort(l0);
        lp[1] = ((uint32_t)__half_as_ushort(l3) << 16) | __half_as_ushort(l2);
    }
    const size_t o = (size_t)row * KXP + c4;
    *(uint2*)(hi + o) = *(const uint2*)hp;
    *(uint2*)(lo + o) = *(const uint2*)lp;
}

__global__ void transpose_w(const float* __restrict__ W,
                            __half* __restrict__ WTh, __half* __restrict__ WTl)
{
    const size_t i = (size_t)blockIdx.x * blockDim.x + threadIdx.x;
    if (i >= (size_t)DIM_L * KXP) return;
    const int n = (int)(i / KXP);
    const int k = (int)(i % KXP);
    const float v = (k < DIM_D) ? W[(size_t)k * DIM_L + n] : 0.0f;
    const __half h = __float2half_rn(v);
    WTh[i] = h;
    WTl[i] = __float2half_rn(v - __half2float(h));
}

__global__ void pad_w(const float* __restrict__ W, __half* __restrict__ WR)
{
    const size_t i = ((size_t)blockIdx.x * blockDim.x + threadIdx.x) * 4;
    if (i >= (size_t)NRP * DIM_L) return;
    const int row = (int)(i / DIM_L);
    uint32_t p[2] = {0, 0};
    if (row < DIM_D) {
        const float4 v = *(const float4*)(W + i);
        p[0] = ((uint32_t)__half_as_ushort(__float2half_rn(v.y)) << 16) |
               __half_as_ushort(__float2half_rn(v.x));
        p[1] = ((uint32_t)__half_as_ushort(__float2half_rn(v.w)) << 16) |
               __half_as_ushort(__float2half_rn(v.z));
    }
    *(uint2*)(WR + i) = *(const uint2*)p;
}

// ============================================================================
extern "C" void kernel_launch(void* const* d_in, const int* in_sizes, int n_in,
                              void* d_out, int out_size) {
    (void)n_in; (void)out_size;

    const float* x = (const float*)d_in[0];
    const float* w = (const float*)d_in[1];
    if (in_sizes[0] == DIM_D * DIM_L) {
        x = (const float*)d_in[1];
        w = (const float*)d_in[0];
    }
    float* out = (float*)d_out;

    __half *Bh, *U0, *U1, *Aa, *Ab, *Gh, *XPh, *XPl, *WTh, *WTl, *WR;
    cudaGetSymbolAddress((void**)&Bh,  g_Bh);
    cudaGetSymbolAddress((void**)&U0,  g_U0);
    cudaGetSymbolAddress((void**)&U1,  g_U1);
    cudaGetSymbolAddress((void**)&Aa,  g_Aa);
    cudaGetSymbolAddress((void**)&Ab,  g_Ab);
    cudaGetSymbolAddress((void**)&Gh,  g_Gh);
    cudaGetSymbolAddress((void**)&XPh, g_XPh);
    cudaGetSymbolAddress((void**)&XPl, g_XPl);
    cudaGetSymbolAddress((void**)&WTh, g_WTh);
    cudaGetSymbolAddress((void**)&WTl, g_WTl);
    cudaGetSymbolAddress((void**)&WR,  g_WR);

    const int SM1 = 2 * 2 * TILE_B;   // 73728 (recon)
    const int SM2 = 2 * 3 * TILE_B;   // 110592 (b, G)
    cudaFuncSetAttribute(lca_step, cudaFuncAttributeMaxDynamicSharedMemorySize, STEP_SMEM);
    cudaFuncSetAttribute(mma_gemm<1, 3>, cudaFuncAttributeMaxDynamicSharedMemorySize, SM1);
    cudaFuncSetAttribute(mma_gemm<2, 2>, cudaFuncAttributeMaxDynamicSharedMemorySize, SM2);
    cudaFuncSetAttribute(mma_gemm<2, 4>, cudaFuncAttributeMaxDynamicSharedMemorySize, SM2);

    // conversions
    transpose_w<<<(DIM_L * KXP + 255) / 256, 256>>>(w, WTh, WTl);
    split_pad_x<<<(int)(((size_t)NUM_B * KXP / 4) / 256), 256>>>(x, XPh, XPl);
    pad_w<<<(NRP * DIM_L / 4 + 255) / 256, 256>>>(w, WR);

    // Gh = fp16( (WTh+WTl) @ WTh - I )
    mma_gemm<2, 4><<<dim3(8, 8), 256, SM2>>>(
        WTh, WTl, WTh, nullptr, Gh, nullptr, nullptr, KXP, KXP, KXP);

    // b = X@W (fp16 2-product, fp32 accum) -> b fp16, u1 fp16, a1 fp16
    mma_gemm<2, 2><<<dim3(8, 128), 256, SM2>>>(
        XPh, XPl, WTh, U0, Aa, Bh, nullptr, KXP, KXP, KXP);

    // steps 2..49 (single-product fp16; u and b fp16 in memory)
    __half *uin = U0, *uout = U1;
    __half *ain = Aa, *aout = Ab;
    for (int s = 0; s < 48; s++) {
        lca_step<<<dim3(8, 128), 256, STEP_SMEM>>>(
            ain, Gh, uin, Bh, uout, aout);
        __half* t;
        t = uin; uin = uout; uout = t;
        t = ain; ain = aout; aout = t;
    }
    // After the final swap, the last-written activations are in `ain`.

    // recon = a_final@W^T (single-product fp16), N=784 guarded
    mma_gemm<1, 3><<<dim3(7, 128), 256, SM1>>>(
        ain, nullptr, WR, nullptr, nullptr, nullptr, out, DIM_L, DIM_L, DIM_L);
}

// round 17
// speedup vs baseline: 1.2179x; 1.0531x over previous
#include <cuda_runtime.h>
#include <cuda_fp16.h>
#include <cstdint>

// Problem constants
#define NUM_B 16384
#define DIM_D 784
#define DIM_L 1024
#define KXP   832          // K of X padded to multiple of 64
#define NRP   896          // recon N padded to multiple of 128
#define LAMBDA 0.3f
#define STEPSZ 0.1f

// ---------------- scratch (__device__ globals; no allocs allowed) ----------
__device__ __half g_Bh[(size_t)NUM_B * DIM_L];        // b fp16
__device__ __half g_U0[(size_t)NUM_B * DIM_L];        // u fp16 ping
__device__ __half g_U1[(size_t)NUM_B * DIM_L];        // u fp16 pong
__device__ __half g_Aa[(size_t)NUM_B * DIM_L];        // a ping
__device__ __half g_Ab[(size_t)NUM_B * DIM_L];        // a pong
__device__ __half g_Gh[DIM_L * DIM_L];                // fp16(G)
__device__ __half g_XPh[(size_t)NUM_B * KXP];         // X hi, K-padded
__device__ __half g_XPl[(size_t)NUM_B * KXP];         // X lo
__device__ __half g_WTh[DIM_L * KXP];                 // W^T hi fp16 [L, KXP]
__device__ __half g_WTl[DIM_L * KXP];                 // W^T lo fp16
__device__ __half g_WR [NRP * DIM_L];                 // W fp16 padded [NRP, L]

__device__ __forceinline__ float lca_thresh(float x) {
    return x > LAMBDA ? x - LAMBDA : 0.0f;
}

// ---------------- baseline-ISA tensor helpers ----------
__device__ __forceinline__ uint32_t smem_u32(const void* p) {
    uint32_t a;
    asm("{ .reg .u64 t; cvta.to.shared.u64 t, %1; cvt.u32.u64 %0, t; }"
        : "=r"(a) : "l"(p));
    return a;
}
__device__ __forceinline__ void cp16(uint32_t dst, const void* src) {
    asm volatile("cp.async.cg.shared.global [%0], [%1], 16;"
                 :: "r"(dst), "l"(src) : "memory");
}
__device__ __forceinline__ void cp_commit() {
    asm volatile("cp.async.commit_group;" ::: "memory");
}
template <int N>
__device__ __forceinline__ void cp_wait() {
    asm volatile("cp.async.wait_group %0;" :: "n"(N) : "memory");
}
__device__ __forceinline__ void ldsm_x4(uint32_t* r, uint32_t a) {
    asm volatile("ldmatrix.sync.aligned.m8n8.x4.shared.b16 {%0,%1,%2,%3}, [%4];"
                 : "=r"(r[0]), "=r"(r[1]), "=r"(r[2]), "=r"(r[3]) : "r"(a));
}
__device__ __forceinline__ void mma_f16(float* c, const uint32_t* a, const uint32_t* b) {
    asm volatile(
        "mma.sync.aligned.m16n8k16.row.col.f32.f16.f16.f32 "
        "{%0,%1,%2,%3}, {%4,%5,%6,%7}, {%8,%9}, {%0,%1,%2,%3};"
        : "+f"(c[0]), "+f"(c[1]), "+f"(c[2]), "+f"(c[3])
        : "r"(a[0]), "r"(a[1]), "r"(a[2]), "r"(a[3]), "r"(b[0]), "r"(b[1]));
}

#define BK   64
#define PAD  72                        // fp16/row (144B pitch, conflict-free)
#define TILE_B (128 * PAD * 2)         // 18432 B
#define NCHUNK (DIM_L / BK)            // 16
#define STEP_SMEM (3 * 2 * TILE_B)     // 110592 B -> 2 CTAs/SM

// ============================================================================
// LCA step kernel (R16 body + row-block offset moff for split chains).
// ============================================================================
__global__ __launch_bounds__(256, 2)
void lca_step(const __half* __restrict__ Ain,
              const __half* __restrict__ Gh,
              const __half* __restrict__ Uin,
              const __half* __restrict__ Bex,
              __half* __restrict__ Uout,
              __half* __restrict__ Aout,
              int moff)
{
    extern __shared__ __align__(16) char dsmem[];
    const uint32_t sb = smem_u32(dsmem);
    constexpr int STAGE_B = 2 * TILE_B;

    const int tid  = threadIdx.x;
    const int lane = tid & 31;
    const int wid  = tid >> 5;
    const int wy   = wid >> 2;
    const int wx   = wid & 3;
    const int m0   = (blockIdx.y + moff) * 128;
    const int n0   = blockIdx.x * 128;

    const int a_row = lane & 15;
    const int a_kh  = lane >> 4;
    uint32_t aoffs[4];
    #pragma unroll
    for (int mi = 0; mi < 4; mi++)
        aoffs[mi] = (uint32_t)((wy * 64 + mi * 16 + a_row) * PAD + a_kh * 8) * 2;

    const int b_nr = ((lane >> 4) & 1) * 8 + (lane & 7);
    const int b_kh = (lane >> 3) & 1;
    uint32_t boffs[2];
    #pragma unroll
    for (int p = 0; p < 2; p++)
        boffs[p] = (uint32_t)((wx * 32 + p * 16 + b_nr) * PAD + b_kh * 8) * 2;

    const int c_row = tid >> 3;
    const int c_col = (tid & 7) * 8;

    float acc[4][4][4];
    #pragma unroll
    for (int i = 0; i < 4; i++)
        #pragma unroll
        for (int j = 0; j < 4; j++)
            #pragma unroll
            for (int q = 0; q < 4; q++) acc[i][j][q] = 0.0f;

    auto issue = [&](int c, int stage) {
        const int k0 = c * BK;
        const uint32_t base = sb + stage * STAGE_B;
        #pragma unroll
        for (int u = 0; u < 4; u++) {
            const int row = c_row + u * 32;
            const uint32_t soff = (uint32_t)(row * PAD + c_col) * 2;
            cp16(base + soff, Ain + (size_t)(m0 + row) * DIM_L + k0 + c_col);
            cp16(base + TILE_B + soff, Gh + (size_t)(n0 + row) * DIM_L + k0 + c_col);
        }
        cp_commit();
    };

    issue(0, 0);

    int st_c = 0, st_n = 1;
    #pragma unroll 1
    for (int c = 0; c < NCHUNK; c++) {
        if (c + 1 < NCHUNK) {
            issue(c + 1, st_n);
            cp_wait<1>();
        } else {
            cp_wait<0>();
        }
        __syncthreads();

        const uint32_t base = sb + st_c * STAGE_B;
        const uint32_t uB = base + TILE_B;

        #pragma unroll
        for (int kk = 0; kk < BK; kk += 16) {
            const uint32_t kb = (uint32_t)kk * 2;
            uint32_t af[4][4];
            uint32_t bq[2][4];
            #pragma unroll
            for (int p = 0; p < 2; p++)
                ldsm_x4(bq[p], uB + boffs[p] + kb);
            #pragma unroll
            for (int mi = 0; mi < 4; mi++)
                ldsm_x4(af[mi], base + aoffs[mi] + kb);
            #pragma unroll
            for (int mi = 0; mi < 4; mi++)
                #pragma unroll
                for (int ni = 0; ni < 4; ni++)
                    mma_f16(acc[mi][ni], af[mi], &bq[ni >> 1][(ni & 1) * 2]);
        }
        st_c = st_n;
        st_n = (st_n == 2) ? 0 : st_n + 1;
    }

    // ---------------- epilogue ----------------
    const int g  = lane >> 2;
    const int tg = lane & 3;
    #pragma unroll
    for (int mi = 0; mi < 4; mi++) {
        #pragma unroll
        for (int ni = 0; ni < 4; ni++) {
            #pragma unroll
            for (int h = 0; h < 2; h++) {
                const int r = m0 + wy * 64 + mi * 16 + g + h * 8;
                const int c0 = n0 + wx * 32 + ni * 8 + tg * 2;
                const size_t idx = (size_t)r * DIM_L + c0;
                const float d0 = acc[mi][ni][h * 2 + 0];
                const float d1 = acc[mi][ni][h * 2 + 1];
                const float2 u2 = __half22float2(*(const __half2*)(Uin + idx));
                const float2 b2 = __half22float2(*(const __half2*)(Bex + idx));
                const float vx = (1.0f - STEPSZ) * u2.x + STEPSZ * b2.x - STEPSZ * d0;
                const float vy = (1.0f - STEPSZ) * u2.y + STEPSZ * b2.y - STEPSZ * d1;
                const __half uh0 = __float2half_rn(vx);
                const __half uh1 = __float2half_rn(vy);
                *(uint32_t*)(Uout + idx) =
                    ((uint32_t)__half_as_ushort(uh1) << 16) | __half_as_ushort(uh0);
                const __half h0 = __float2half_rn(lca_thresh(vx));
                const __half h1 = __float2half_rn(lca_thresh(vy));
                *(uint32_t*)(Aout + idx) =
                    ((uint32_t)__half_as_ushort(h1) << 16) | __half_as_ushort(h0);
            }
        }
    }
}

// ============================================================================
// fp16 mma GEMM (2-stage) for G, b, recon. (unchanged from R16)
// ============================================================================
template<int NPROD, int EPI>
__global__ __launch_bounds__(256, 2)
void mma_gemm(const __half* __restrict__ A0p, const __half* __restrict__ A1p,
              const __half* __restrict__ Bmp,
              __half* __restrict__ Uout,
              __half* __restrict__ Aout,
              __half* __restrict__ Bout,
              float* __restrict__ Cout,
              int Kdim, int ldA, int ldB)
{
    constexpr int STAGE_B = (NPROD + 1) * TILE_B;
    extern __shared__ __align__(16) char dsmem[];
    const uint32_t sb = smem_u32(dsmem);

    const int tid  = threadIdx.x;
    const int lane = tid & 31;
    const int wid  = tid >> 5;
    const int wy   = wid >> 2;
    const int wx   = wid & 3;
    const int m0   = blockIdx.y * 128;
    const int n0   = blockIdx.x * 128;
    const int NC   = Kdim >> 6;

    const int a_row = lane & 15;
    const int a_kh  = lane >> 4;
    uint32_t aoffs[4];
    #pragma unroll
    for (int mi = 0; mi < 4; mi++)
        aoffs[mi] = (uint32_t)((wy * 64 + mi * 16 + a_row) * PAD + a_kh * 8) * 2;

    const int b_nr = ((lane >> 4) & 1) * 8 + (lane & 7);
    const int b_kh = (lane >> 3) & 1;
    uint32_t boffs[2];
    #pragma unroll
    for (int p = 0; p < 2; p++)
        boffs[p] = (uint32_t)((wx * 32 + p * 16 + b_nr) * PAD + b_kh * 8) * 2;

    const int c_row = tid >> 3;
    const int c_col = (tid & 7) * 8;

    float acc[4][4][4];
    #pragma unroll
    for (int i = 0; i < 4; i++)
        #pragma unroll
        for (int j = 0; j < 4; j++)
            #pragma unroll
            for (int q = 0; q < 4; q++) acc[i][j][q] = 0.0f;

    auto issue = [&](int c, int stage) {
        const int k0 = c * BK;
        const uint32_t base = sb + stage * STAGE_B;
        #pragma unroll
        for (int t = 0; t < 4; t++) {
            const int row = c_row + t * 32;
            const uint32_t soff = (uint32_t)(row * PAD + c_col) * 2;
            cp16(base + soff, A0p + (size_t)(m0 + row) * ldA + k0 + c_col);
            if (NPROD == 2)
                cp16(base + TILE_B + soff, A1p + (size_t)(m0 + row) * ldA + k0 + c_col);
            cp16(base + NPROD * TILE_B + soff,
                 Bmp + (size_t)(n0 + row) * ldB + k0 + c_col);
        }
        cp_commit();
    };

    issue(0, 0);

    #pragma unroll 1
    for (int c = 0; c < NC; c++) {
        if (c + 1 < NC) {
            issue(c + 1, (c + 1) & 1);
            cp_wait<1>();
        } else {
            cp_wait<0>();
        }
        __syncthreads();

        const uint32_t base = sb + (c & 1) * STAGE_B;
        const uint32_t uB = base + NPROD * TILE_B;

        #pragma unroll
        for (int kk = 0; kk < BK; kk += 16) {
            const uint32_t kb = (uint32_t)kk * 2;
            uint32_t af[4][4];
            uint32_t bq[2][4];
            #pragma unroll
            for (int p = 0; p < 2; p++)
                ldsm_x4(bq[p], uB + boffs[p] + kb);
            #pragma unroll
            for (int mi = 0; mi < 4; mi++)
                ldsm_x4(af[mi], base + aoffs[mi] + kb);
            #pragma unroll
            for (int mi = 0; mi < 4; mi++)
                #pragma unroll
                for (int ni = 0; ni < 4; ni++)
                    mma_f16(acc[mi][ni], af[mi], &bq[ni >> 1][(ni & 1) * 2]);
            if (NPROD == 2) {
                #pragma unroll
                for (int mi = 0; mi < 4; mi++)
                    ldsm_x4(af[mi], base + TILE_B + aoffs[mi] + kb);
                #pragma unroll
                for (int mi = 0; mi < 4; mi++)
                    #pragma unroll
                    for (int ni = 0; ni < 4; ni++)
                        mma_f16(acc[mi][ni], af[mi], &bq[ni >> 1][(ni & 1) * 2]);
            }
        }
        __syncthreads();
    }

    const int g  = lane >> 2;
    const int tg = lane & 3;
    #pragma unroll
    for (int mi = 0; mi < 4; mi++) {
        #pragma unroll
        for (int ni = 0; ni < 4; ni++) {
            #pragma unroll
            for (int h = 0; h < 2; h++) {
                const int r = m0 + wy * 64 + mi * 16 + g + h * 8;
                const int c0 = n0 + wx * 32 + ni * 8 + tg * 2;
                float d0 = acc[mi][ni][h * 2 + 0];
                float d1 = acc[mi][ni][h * 2 + 1];
                if (EPI == 2) {
                    const size_t idx = (size_t)r * DIM_L + c0;
                    const __half bh0 = __float2half_rn(d0);
                    const __half bh1 = __float2half_rn(d1);
                    *(uint32_t*)(Bout + idx) =
                        ((uint32_t)__half_as_ushort(bh1) << 16) | __half_as_ushort(bh0);
                    const float vx = STEPSZ * d0, vy = STEPSZ * d1;
                    const __half uh0 = __float2half_rn(vx);
                    const __half uh1 = __float2half_rn(vy);
                    *(uint32_t*)(Uout + idx) =
                        ((uint32_t)__half_as_ushort(uh1) << 16) | __half_as_ushort(uh0);
                    const __half h0 = __float2half_rn(lca_thresh(vx));
                    const __half h1 = __float2half_rn(lca_thresh(vy));
                    *(uint32_t*)(Aout + idx) =
                        ((uint32_t)__half_as_ushort(h1) << 16) | __half_as_ushort(h0);
                } else if (EPI == 3) {
                    if (c0 < DIM_D)
                        *(float2*)(Cout + (size_t)r * DIM_D + c0) = make_float2(d0, d1);
                } else { // EPI == 4
                    if (r == c0 + 0) d0 -= 1.0f;
                    if (r == c0 + 1) d1 -= 1.0f;
                    const __half h0 = __float2half_rn(d0);
                    const __half h1 = __float2half_rn(d1);
                    *(uint32_t*)(Aout + (size_t)r * DIM_L + c0) =
                        ((uint32_t)__half_as_ushort(h1) << 16) | __half_as_ushort(h0);
                }
            }
        }
    }
}

// ---------------- conversion kernels (one-time) ----------------
__global__ void split_pad_x(const float* __restrict__ X,
                            __half* __restrict__ hi, __half* __restrict__ lo)
{
    const size_t v = (size_t)blockIdx.x * blockDim.x + threadIdx.x;
    const int row = (int)(v / (KXP / 4));
    const int c4  = (int)(v % (KXP / 4)) * 4;
    uint32_t hp[2] = {0, 0}, lp[2] = {0, 0};
    if (c4 < DIM_D) {
        const float4 x = *(const float4*)(X + (size_t)row * DIM_D + c4);
        const __half h0 = __float2half_rn(x.x), h1 = __float2half_rn(x.y);
        const __half h2 = __float2half_rn(x.z), h3 = __float2half_rn(x.w);
        const __half l0 = __float2half_rn(x.x - __half2float(h0));
        const __half l1 = __float2half_rn(x.y - __half2float(h1));
        const __half l2 = __float2half_rn(x.z - __half2float(h2));
        const __half l3 = __float2half_rn(x.w - __half2float(h3));
        hp[0] = ((uint32_t)__half_as_ushort(h1) << 16) | __half_as_ushort(h0);
        hp[1] = ((uint32_t)__half_as_ushort(h3) << 16) | __half_as_ushort(h2);
        lp[0] = ((uint32_t)__half_as_ushort(l1) << 16) | __half_as_ushort(l0);
        lp[1] = ((uint32_t)__half_as_ushort(l3) << 16) | __half_as_ushort(l2);
    }
    const size_t o = (size_t)row * KXP + c4;
    *(uint2*)(hi + o) = *(const uint2*)hp;
    *(uint2*)(lo + o) = *(const uint2*)lp;
}

__global__ void transpose_w(const float* __restrict__ W,
                            __half* __restrict__ WTh, __half* __restrict__ WTl)
{
    const size_t i = (size_t)blockIdx.x * blockDim.x + threadIdx.x;
    if (i >= (size_t)DIM_L * KXP) return;
    const int n = (int)(i / KXP);
    const int k = (int)(i % KXP);
    const float v = (k < DIM_D) ? W[(size_t)k * DIM_L + n] : 0.0f;
    const __half h = __float2half_rn(v);
    WTh[i] = h;
    WTl[i] = __float2half_rn(v - __half2float(h));
}

__global__ void pad_w(const float* __restrict__ W, __half* __restrict__ WR)
{
    const size_t i = ((size_t)blockIdx.x * blockDim.x + threadIdx.x) * 4;
    if (i >= (size_t)NRP * DIM_L) return;
    const int row = (int)(i / DIM_L);
    uint32_t p[2] = {0, 0};
    if (row < DIM_D) {
        const float4 v = *(const float4*)(W + i);
        p[0] = ((uint32_t)__half_as_ushort(__float2half_rn(v.y)) << 16) |
               __half_as_ushort(__float2half_rn(v.x));
        p[1] = ((uint32_t)__half_as_ushort(__float2half_rn(v.w)) << 16) |
               __half_as_ushort(__float2half_rn(v.z));
    }
    *(uint2*)(WR + i) = *(const uint2*)p;
}

// ============================================================================
extern "C" void kernel_launch(void* const* d_in, const int* in_sizes, int n_in,
                              void* d_out, int out_size) {
    (void)n_in; (void)out_size;

    const float* x = (const float*)d_in[0];
    const float* w = (const float*)d_in[1];
    if (in_sizes[0] == DIM_D * DIM_L) {
        x = (const float*)d_in[1];
        w = (const float*)d_in[0];
    }
    float* out = (float*)d_out;

    __half *Bh, *U0, *U1, *Aa, *Ab, *Gh, *XPh, *XPl, *WTh, *WTl, *WR;
    cudaGetSymbolAddress((void**)&Bh,  g_Bh);
    cudaGetSymbolAddress((void**)&U0,  g_U0);
    cudaGetSymbolAddress((void**)&U1,  g_U1);
    cudaGetSymbolAddress((void**)&Aa,  g_Aa);
    cudaGetSymbolAddress((void**)&Ab,  g_Ab);
    cudaGetSymbolAddress((void**)&Gh,  g_Gh);
    cudaGetSymbolAddress((void**)&XPh, g_XPh);
    cudaGetSymbolAddress((void**)&XPl, g_XPl);
    cudaGetSymbolAddress((void**)&WTh, g_WTh);
    cudaGetSymbolAddress((void**)&WTl, g_WTl);
    cudaGetSymbolAddress((void**)&WR,  g_WR);

    const int SM1 = 2 * 2 * TILE_B;   // 73728 (recon)
    const int SM2 = 2 * 3 * TILE_B;   // 110592 (b, G)
    cudaFuncSetAttribute(lca_step, cudaFuncAttributeMaxDynamicSharedMemorySize, STEP_SMEM);
    cudaFuncSetAttribute(mma_gemm<1, 3>, cudaFuncAttributeMaxDynamicSharedMemorySize, SM1);
    cudaFuncSetAttribute(mma_gemm<2, 2>, cudaFuncAttributeMaxDynamicSharedMemorySize, SM2);
    cudaFuncSetAttribute(mma_gemm<2, 4>, cudaFuncAttributeMaxDynamicSharedMemorySize, SM2);

    // streams/events created once, reused (graph fork/join pattern)
    static cudaStream_t sT = nullptr, sB = nullptr;
    static cudaEvent_t eFork = nullptr, eT = nullptr, eB = nullptr;
    if (!sT) {
        cudaStreamCreateWithFlags(&sT, cudaStreamNonBlocking);
        cudaStreamCreateWithFlags(&sB, cudaStreamNonBlocking);
        cudaEventCreateWithFlags(&eFork, cudaEventDisableTiming);
        cudaEventCreateWithFlags(&eT,    cudaEventDisableTiming);
        cudaEventCreateWithFlags(&eB,    cudaEventDisableTiming);
    }

    // conversions (default stream)
    transpose_w<<<(DIM_L * KXP + 255) / 256, 256>>>(w, WTh, WTl);
    split_pad_x<<<(int)(((size_t)NUM_B * KXP / 4) / 256), 256>>>(x, XPh, XPl);
    pad_w<<<(NRP * DIM_L / 4 + 255) / 256, 256>>>(w, WR);

    // Gh = fp16( (WTh+WTl) @ WTh - I )
    mma_gemm<2, 4><<<dim3(8, 8), 256, SM2>>>(
        WTh, WTl, WTh, nullptr, Gh, nullptr, nullptr, KXP, KXP, KXP);

    // b = X@W -> b fp16, u1 fp16, a1 fp16
    mma_gemm<2, 2><<<dim3(8, 128), 256, SM2>>>(
        XPh, XPl, WTh, U0, Aa, Bh, nullptr, KXP, KXP, KXP);

    // ---- fork: two independent row-half chains on separate streams ----
    cudaEventRecord(eFork, 0);
    cudaStreamWaitEvent(sT, eFork, 0);
    cudaStreamWaitEvent(sB, eFork, 0);

    __half *uin = U0, *uout = U1;
    __half *ain = Aa, *aout = Ab;
    for (int s = 0; s < 48; s++) {
        lca_step<<<dim3(8, 64), 256, STEP_SMEM, sT>>>(
            ain, Gh, uin, Bh, uout, aout, 0);    // rows 0..8191
        lca_step<<<dim3(8, 64), 256, STEP_SMEM, sB>>>(
            ain, Gh, uin, Bh, uout, aout, 64);   // rows 8192..16383
        __half* t;
        t = uin; uin = uout; uout = t;
        t = ain; ain = aout; aout = t;
    }
    cudaEventRecord(eT, sT);
    cudaEventRecord(eB, sB);
    cudaStreamWaitEvent(0, eT, 0);
    cudaStreamWaitEvent(0, eB, 0);

    // After the final swap, the last-written activations are in `ain`.
    // recon = a_final@W^T (single-product fp16), N=784 guarded
    mma_gemm<1, 3><<<dim3(7, 128), 256, SM1>>>(
        ain, nullptr, WR, nullptr, nullptr, nullptr, out, DIM_L, DIM_L, DIM_L);
}